// round 13
// baseline (speedup 1.0000x reference)
#include <cuda_runtime.h>
#include <cstdint>

#define BATCH 8
#define SEQ   1024
#define DIM   1024
#define HEADS 16
#define DH    64
#define INNER 1024
#define QKV_STRIDE (3 * INNER)

// Scratch (static device arrays: the sanctioned no-alloc workaround)
__device__ uint32_t g_qkv[(size_t)BATCH * SEQ * 3 * INNER];   // tf32 bits
__device__ uint32_t g_att[(size_t)BATCH * SEQ * INNER];       // tf32 bits
__device__ uint32_t g_xt[(size_t)BATCH * SEQ * DIM];          // x as tf32 bits
__device__ uint32_t g_wqkvt[(size_t)DIM * 3 * INNER];         // w_qkv as tf32 bits
__device__ uint32_t g_woutt[(size_t)INNER * DIM];             // w_out as tf32 bits

// ---------------------------------------------------------------------------
// helpers
// ---------------------------------------------------------------------------
__device__ __forceinline__ uint32_t f2t(float x) {
    uint32_t r;
    asm("cvt.rna.tf32.f32 %0, %1;" : "=r"(r) : "f"(x));
    return r;
}
__device__ __forceinline__ uint4 f2t4(float4 v) {
    return make_uint4(f2t(v.x), f2t(v.y), f2t(v.z), f2t(v.w));
}
__device__ __forceinline__ float ex2(float x) {
    float r;
    asm("ex2.approx.ftz.f32 %0, %1;" : "=f"(r) : "f"(x));
    return r;
}
__device__ __forceinline__ uint32_t smem_u32(const void* p) {
    uint32_t a;
    asm("{ .reg .u64 t; cvta.to.shared.u64 t, %1; cvt.u32.u64 %0, t; }" : "=r"(a) : "l"(p));
    return a;
}
__device__ __forceinline__ void cpasync16(uint32_t s, const void* g) {
    asm volatile("cp.async.cg.shared.global [%0], [%1], 16;" :: "r"(s), "l"(g));
}

// m16n8k8 tf32 MMA, fp32 accumulate. A row-major, B col-major.
__device__ __forceinline__ void mma8(float* c, const uint32_t* a, const uint32_t* b) {
    asm volatile(
        "mma.sync.aligned.m16n8k8.row.col.f32.tf32.tf32.f32 "
        "{%0,%1,%2,%3}, {%4,%5,%6,%7}, {%8,%9}, {%0,%1,%2,%3};\n"
        : "+f"(c[0]), "+f"(c[1]), "+f"(c[2]), "+f"(c[3])
        : "r"(a[0]), "r"(a[1]), "r"(a[2]), "r"(a[3]), "r"(b[0]), "r"(b[1]));
}

// ---------------------------------------------------------------------------
// fused fp32 -> tf32-bits converter for all three operand arrays
// ---------------------------------------------------------------------------
__global__ void conv_all(const float4* __restrict__ i0, uint4* __restrict__ o0, int n0,
                         const float4* __restrict__ i1, uint4* __restrict__ o1, int n1,
                         const float4* __restrict__ i2, uint4* __restrict__ o2, int n2)
{
    const int stride = gridDim.x * blockDim.x;
    const int t0 = blockIdx.x * blockDim.x + threadIdx.x;
    for (int i = t0; i < n0; i += stride) o0[i] = f2t4(i0[i]);
    for (int i = t0; i < n1; i += stride) o1[i] = f2t4(i1[i]);
    for (int i = t0; i < n2; i += stride) o2[i] = f2t4(i2[i]);
}

// ---------------------------------------------------------------------------
// tf32 GEMM on pre-converted bits: C = A*B (+bias).  (R11 config — known good)
// BM=BN=128, BK=16, 256 threads, 8 warps (2m x 4n), warp tile 64x32.
// 4-stage cp.async pipeline; As [m][k] LDA=20, Bs [k][n] LDB=136.
// ---------------------------------------------------------------------------
#define LDA 20
#define LDB 136
#define STG_WORDS (128 * LDA + 16 * LDB)          // 4736 words / stage
#define GEMM_SMEM (4 * STG_WORDS * 4)             // 75776 bytes

__global__ __launch_bounds__(256, 2) void gemm_tf32(
    const uint32_t* __restrict__ A, const uint32_t* __restrict__ B,
    const float* __restrict__ bias, uint32_t* __restrict__ C,
    int M, int N, int K, int out_tf32)
{
    extern __shared__ uint32_t sm[];
    const uint32_t sbase = smem_u32(sm);

    const int tid  = threadIdx.x;
    const int lane = tid & 31;
    const int warp = tid >> 5;
    const int row0 = blockIdx.y * 128;
    const int col0 = blockIdx.x * 128;

    const int wm = (warp >> 2) * 64;
    const int wn = (warp & 3) * 32;
    const int r4 = lane >> 2, c4 = lane & 3;

    float acc[4][4][4] = {};

    const int nch = K / 16;

    auto issue = [&](int c, int st) {
        const int kt = c * 16;
        const uint32_t abase = sbase + st * STG_WORDS * 4;
        const uint32_t bbase = abase + 128 * LDA * 4;
        #pragma unroll
        for (int it = 0; it < 2; it++) {
            int idx = tid + it * 256;                 // 0..511
            int m = idx >> 2, k0 = (idx & 3) * 4;
            cpasync16(abase + (m * LDA + k0) * 4,
                      A + (size_t)(row0 + m) * K + kt + k0);
            int kr = idx >> 5, nq = (idx & 31) * 4;
            cpasync16(bbase + (kr * LDB + nq) * 4,
                      B + (size_t)(kt + kr) * N + col0 + nq);
        }
        asm volatile("cp.async.commit_group;" ::: "memory");
    };

    issue(0, 0);
    issue(1, 1);
    issue(2, 2);

    for (int c = 0; c < nch; c++) {
        const int rem = nch - 1 - c;
        if (rem >= 2)      asm volatile("cp.async.wait_group 2;" ::: "memory");
        else if (rem == 1) asm volatile("cp.async.wait_group 1;" ::: "memory");
        else               asm volatile("cp.async.wait_group 0;" ::: "memory");
        __syncthreads();

        const uint32_t* As = sm + (c & 3) * STG_WORDS;
        const uint32_t* Bs = As + 128 * LDA;

        #pragma unroll
        for (int kk = 0; kk < 2; kk++) {
            const int kc = kk * 8 + c4;
            uint32_t a[4][4], b[4][2];
            #pragma unroll
            for (int fm = 0; fm < 4; fm++) {
                const int r = wm + fm * 16 + r4;
                a[fm][0] = As[r * LDA + kc];
                a[fm][1] = As[(r + 8) * LDA + kc];
                a[fm][2] = As[r * LDA + kc + 4];
                a[fm][3] = As[(r + 8) * LDA + kc + 4];
            }
            #pragma unroll
            for (int fn = 0; fn < 4; fn++) {
                const int n = wn + fn * 8 + r4;
                b[fn][0] = Bs[kc * LDB + n];
                b[fn][1] = Bs[(kc + 4) * LDB + n];
            }
            #pragma unroll
            for (int fm = 0; fm < 4; fm++)
                #pragma unroll
                for (int fn = 0; fn < 4; fn++)
                    mma8(acc[fm][fn], a[fm], b[fn]);
        }

        if (c + 3 < nch) issue(c + 3, (c + 3) & 3);
    }

    // Epilogue
    #pragma unroll
    for (int fm = 0; fm < 4; fm++) {
        #pragma unroll
        for (int fn = 0; fn < 4; fn++) {
            const int row = row0 + wm + fm * 16 + r4;
            const int col = col0 + wn + fn * 8 + c4 * 2;
            uint32_t* c0 = C + (size_t)row * N + col;
            uint32_t* c1 = C + (size_t)(row + 8) * N + col;
            if (out_tf32) {
                *(uint2*)c0 = make_uint2(f2t(acc[fm][fn][0]), f2t(acc[fm][fn][1]));
                *(uint2*)c1 = make_uint2(f2t(acc[fm][fn][2]), f2t(acc[fm][fn][3]));
            } else {
                float b0 = 0.f, b1 = 0.f;
                if (bias) { b0 = bias[col]; b1 = bias[col + 1]; }
                *(float2*)c0 = make_float2(acc[fm][fn][0] + b0, acc[fm][fn][1] + b1);
                *(float2*)c1 = make_float2(acc[fm][fn][2] + b0, acc[fm][fn][3] + b1);
            }
        }
    }
}

// ---------------------------------------------------------------------------
// Flash attention. CTA = 128 query rows of one (b,h); 128 threads, 4 warps,
// warp owns 32 rows (2 m-tiles of 16) x 64 cols.
// S-phase split by m-tile to cut live registers (s: 64->32 regs) so that
// __launch_bounds__(128, 3) yields 3 CTAs/SM. K tile via cp.async; V manual
// transpose with XOR swizzle. exp2-domain softmax. PV shares V b-frags.
// ---------------------------------------------------------------------------
#define KVPAD 68
#define ATTN_SMEM ((2 * 64 * KVPAD + 4 * 2048) * 4)   // 67584 bytes

__global__ __launch_bounds__(128, 3) void attn_tf32(
    const uint32_t* __restrict__ qkv, uint32_t* __restrict__ out)
{
    extern __shared__ uint32_t sm[];
    uint32_t* Ksm = sm;                     // [j(64)][KVPAD]
    uint32_t* Vsm = sm + 64 * KVPAD;        // [d(64)][ j ^ 4*((d>>3)&7) ]
    uint32_t* Psm = sm + 2 * 64 * KVPAD;    // per-warp 2048 words
    const uint32_t ksm_base = smem_u32(sm);

    const int tid  = threadIdx.x;
    const int lane = tid & 31;
    const int warp = tid >> 5;
    const int r4 = lane >> 2, c4 = lane & 3;
    const int qt = blockIdx.x, h = blockIdx.y, b = blockIdx.z;
    const int qr0 = qt * 128 + warp * 32;

    const uint32_t* qbase = qkv + ((size_t)b * SEQ + qr0) * QKV_STRIDE + h * DH;
    const uint32_t* kbase = qkv + (size_t)b * SEQ * QKV_STRIDE + INNER     + h * DH;
    const uint32_t* vbase = qkv + (size_t)b * SEQ * QKV_STRIDE + 2 * INNER + h * DH;

    const float QS = 0.125f * 1.44269504088896340736f;
    uint32_t qf[8][2][4];
    #pragma unroll
    for (int kb = 0; kb < 8; kb++) {
        const int col = kb * 8 + c4;
        #pragma unroll
        for (int m2 = 0; m2 < 2; m2++) {
            const int rb = m2 * 16;
            qf[kb][m2][0] = f2t(__uint_as_float(qbase[(size_t)(rb + r4) * QKV_STRIDE + col]) * QS);
            qf[kb][m2][1] = f2t(__uint_as_float(qbase[(size_t)(rb + r4 + 8) * QKV_STRIDE + col]) * QS);
            qf[kb][m2][2] = f2t(__uint_as_float(qbase[(size_t)(rb + r4) * QKV_STRIDE + col + 4]) * QS);
            qf[kb][m2][3] = f2t(__uint_as_float(qbase[(size_t)(rb + r4 + 8) * QKV_STRIDE + col + 4]) * QS);
        }
    }

    float mrun[2][2] = {{-3.0e38f, -3.0e38f}, {-3.0e38f, -3.0e38f}};
    float lrun[2][2] = {{0.f, 0.f}, {0.f, 0.f}};
    float o[2][8][4] = {};
    uint32_t* Pw = Psm + warp * 2048;

    for (int t = 0; t < 16; t++) {
        __syncthreads();   // previous tile fully consumed
        const uint32_t* kt_ = kbase + (size_t)t * 64 * QKV_STRIDE;
        const uint32_t* vt_ = vbase + (size_t)t * 64 * QKV_STRIDE;
        // K tile via cp.async (no transform needed)
        #pragma unroll
        for (int it = 0; it < 8; it++) {
            int idx = it * 128 + tid;            // 0..1023 16B chunks
            int j = idx >> 4, dq = idx & 15;
            cpasync16(ksm_base + (j * KVPAD + dq * 4) * 4,
                      kt_ + (size_t)j * QKV_STRIDE + dq * 4);
        }
        asm volatile("cp.async.commit_group;" ::: "memory");
        // V tile: manual swizzled transpose
        #pragma unroll
        for (int it = 0; it < 8; it++) {
            int idx = it * 128 + tid;
            int j = idx >> 4, dq = idx & 15;
            uint4 vv = *(const uint4*)(vt_ + (size_t)j * QKV_STRIDE + dq * 4);
            const int swc = j ^ (4 * ((dq >> 1) & 7));
            Vsm[(dq * 4 + 0) * KVPAD + swc] = vv.x;
            Vsm[(dq * 4 + 1) * KVPAD + swc] = vv.y;
            Vsm[(dq * 4 + 2) * KVPAD + swc] = vv.z;
            Vsm[(dq * 4 + 3) * KVPAD + swc] = vv.w;
        }
        asm volatile("cp.async.wait_group 0;" ::: "memory");
        __syncthreads();

        // ---- per m-tile: S = Q*K^T, online softmax, repack ----
        #pragma unroll
        for (int m2 = 0; m2 < 2; m2++) {
            float s[8][4] = {};
            #pragma unroll
            for (int kb = 0; kb < 8; kb++) {
                #pragma unroll
                for (int fn = 0; fn < 8; fn++) {
                    uint32_t bb[2];
                    bb[0] = Ksm[(fn * 8 + r4) * KVPAD + kb * 8 + c4];
                    bb[1] = Ksm[(fn * 8 + r4) * KVPAD + kb * 8 + c4 + 4];
                    mma8(s[fn], qf[kb][m2], bb);
                }
            }

            float mt0 = -3.0e38f, mt1 = -3.0e38f;
            #pragma unroll
            for (int fn = 0; fn < 8; fn++) {
                mt0 = fmaxf(mt0, fmaxf(s[fn][0], s[fn][1]));
                mt1 = fmaxf(mt1, fmaxf(s[fn][2], s[fn][3]));
            }
            mt0 = fmaxf(mt0, __shfl_xor_sync(0xffffffffu, mt0, 1));
            mt0 = fmaxf(mt0, __shfl_xor_sync(0xffffffffu, mt0, 2));
            mt1 = fmaxf(mt1, __shfl_xor_sync(0xffffffffu, mt1, 1));
            mt1 = fmaxf(mt1, __shfl_xor_sync(0xffffffffu, mt1, 2));
            const float mn0 = fmaxf(mrun[m2][0], mt0);
            const float mn1 = fmaxf(mrun[m2][1], mt1);
            const float al0 = ex2(mrun[m2][0] - mn0);
            const float al1 = ex2(mrun[m2][1] - mn1);
            float ls0 = 0.f, ls1 = 0.f;
            #pragma unroll
            for (int fn = 0; fn < 8; fn++) {
                s[fn][0] = ex2(s[fn][0] - mn0); ls0 += s[fn][0];
                s[fn][1] = ex2(s[fn][1] - mn0); ls0 += s[fn][1];
                s[fn][2] = ex2(s[fn][2] - mn1); ls1 += s[fn][2];
                s[fn][3] = ex2(s[fn][3] - mn1); ls1 += s[fn][3];
            }
            ls0 += __shfl_xor_sync(0xffffffffu, ls0, 1);
            ls0 += __shfl_xor_sync(0xffffffffu, ls0, 2);
            ls1 += __shfl_xor_sync(0xffffffffu, ls1, 1);
            ls1 += __shfl_xor_sync(0xffffffffu, ls1, 2);
            lrun[m2][0] = lrun[m2][0] * al0 + ls0;
            lrun[m2][1] = lrun[m2][1] * al1 + ls1;
            mrun[m2][0] = mn0;  mrun[m2][1] = mn1;

            #pragma unroll
            for (int fn = 0; fn < 8; fn++) {
                o[m2][fn][0] *= al0; o[m2][fn][1] *= al0;
                o[m2][fn][2] *= al1; o[m2][fn][3] *= al1;
            }

            const int lp0 = r4 * 4 + 2 * (c4 & 1);
            const int rb  = 2 * (c4 >> 1);
            uint32_t* Pm = Pw + m2 * 1024;
            #pragma unroll
            for (int fn = 0; fn < 8; fn++) {
                Pm[(fn * 4 + rb) * 32 + lp0]         = f2t(s[fn][0]);
                Pm[(fn * 4 + rb) * 32 + lp0 + 1]     = f2t(s[fn][1]);
                Pm[(fn * 4 + rb + 1) * 32 + lp0]     = f2t(s[fn][2]);
                Pm[(fn * 4 + rb + 1) * 32 + lp0 + 1] = f2t(s[fn][3]);
            }
        }
        __syncwarp();

        // ---- O += P * V (V b-frags shared across m2; swizzled loads) ----
        #pragma unroll
        for (int kb = 0; kb < 8; kb++) {
            uint32_t a0[4], a1[4];
            #pragma unroll
            for (int r = 0; r < 4; r++) {
                a0[r] = Pw[(kb * 4 + r) * 32 + lane];
                a1[r] = Pw[1024 + (kb * 4 + r) * 32 + lane];
            }
            #pragma unroll
            for (int fn = 0; fn < 8; fn++) {
                const int d = fn * 8 + r4;
                const int sw = 4 * fn;
                uint32_t bb[2];
                bb[0] = Vsm[d * KVPAD + ((kb * 8 + c4) ^ sw)];
                bb[1] = Vsm[d * KVPAD + ((kb * 8 + c4 + 4) ^ sw)];
                mma8(o[0][fn], a0, bb);
                mma8(o[1][fn], a1, bb);
            }
        }
        __syncwarp();   // P reads done before next tile's P writes
    }

    // ---- normalize, emit tf32 bits for GEMM2 ----
    #pragma unroll
    for (int m2 = 0; m2 < 2; m2++) {
        const float inv0 = 1.f / lrun[m2][0];
        const float inv1 = 1.f / lrun[m2][1];
        uint32_t* ob = out + ((size_t)b * SEQ + qr0 + m2 * 16) * INNER + h * DH;
        #pragma unroll
        for (int fn = 0; fn < 8; fn++) {
            const int col = fn * 8 + 2 * c4;
            *(uint2*)&ob[(size_t)r4 * INNER + col] =
                make_uint2(f2t(o[m2][fn][0] * inv0), f2t(o[m2][fn][1] * inv0));
            *(uint2*)&ob[(size_t)(r4 + 8) * INNER + col] =
                make_uint2(f2t(o[m2][fn][2] * inv1), f2t(o[m2][fn][3] * inv1));
        }
    }
}

// ---------------------------------------------------------------------------
// Launch
// ---------------------------------------------------------------------------
extern "C" void kernel_launch(void* const* d_in, const int* in_sizes, int n_in,
                              void* d_out, int out_size)
{
    const float* x      = (const float*)d_in[0];
    const float* w_qkv  = (const float*)d_in[1];
    const float* w_out  = (const float*)d_in[2];
    const float* b_out  = (const float*)d_in[3];
    uint32_t* out = (uint32_t*)d_out;

    uint32_t *qkv, *att, *xt, *wqkvt, *woutt;
    cudaGetSymbolAddress((void**)&qkv,   g_qkv);
    cudaGetSymbolAddress((void**)&att,   g_att);
    cudaGetSymbolAddress((void**)&xt,    g_xt);
    cudaGetSymbolAddress((void**)&wqkvt, g_wqkvt);
    cudaGetSymbolAddress((void**)&woutt, g_woutt);

    const int M = BATCH * SEQ;   // 8192

    cudaFuncSetAttribute(gemm_tf32, cudaFuncAttributeMaxDynamicSharedMemorySize, GEMM_SMEM);
    cudaFuncSetAttribute(attn_tf32, cudaFuncAttributeMaxDynamicSharedMemorySize, ATTN_SMEM);

    // 0) pre-convert all operands to tf32 bits (single fused launch)
    conv_all<<<2048, 256>>>(
        (const float4*)x,     (uint4*)xt,    (int)((size_t)M * DIM / 4),
        (const float4*)w_qkv, (uint4*)wqkvt, (int)((size_t)DIM * 3 * INNER / 4),
        (const float4*)w_out, (uint4*)woutt, (int)((size_t)INNER * DIM / 4));

    // 1) QKV projection (emits tf32 bits)
    gemm_tf32<<<dim3(3 * INNER / 128, M / 128), 256, GEMM_SMEM>>>(
        xt, wqkvt, nullptr, qkv, M, 3 * INNER, DIM, 1);

    // 2) Flash attention (emits tf32 bits)
    attn_tf32<<<dim3(SEQ / 128, HEADS, BATCH), 128, ATTN_SMEM>>>(qkv, att);

    // 3) Output projection (fp32 + bias, final)
    gemm_tf32<<<dim3(DIM / 128, M / 128), 256, GEMM_SMEM>>>(
        att, woutt, b_out, out, M, DIM, INNER, 0);
}

// round 14
// speedup vs baseline: 1.0259x; 1.0259x over previous
#include <cuda_runtime.h>
#include <cstdint>

#define BATCH 8
#define SEQ   1024
#define DIM   1024
#define HEADS 16
#define DH    64
#define INNER 1024
#define QKV_STRIDE (3 * INNER)

// Scratch (static device arrays: the sanctioned no-alloc workaround)
__device__ uint32_t g_qkv[(size_t)BATCH * SEQ * 3 * INNER];   // tf32 bits
__device__ uint32_t g_att[(size_t)BATCH * SEQ * INNER];       // tf32 bits
__device__ uint32_t g_xt[(size_t)BATCH * SEQ * DIM];          // x as tf32 bits
__device__ uint32_t g_wqkvt[(size_t)DIM * 3 * INNER];         // w_qkv as tf32 bits
__device__ uint32_t g_woutt[(size_t)INNER * DIM];             // w_out as tf32 bits

// ---------------------------------------------------------------------------
// helpers
// ---------------------------------------------------------------------------
__device__ __forceinline__ uint32_t f2t(float x) {
    uint32_t r;
    asm("cvt.rna.tf32.f32 %0, %1;" : "=r"(r) : "f"(x));
    return r;
}
__device__ __forceinline__ uint4 f2t4(float4 v) {
    return make_uint4(f2t(v.x), f2t(v.y), f2t(v.z), f2t(v.w));
}
__device__ __forceinline__ float ex2(float x) {
    float r;
    asm("ex2.approx.ftz.f32 %0, %1;" : "=f"(r) : "f"(x));
    return r;
}
__device__ __forceinline__ uint32_t smem_u32(const void* p) {
    uint32_t a;
    asm("{ .reg .u64 t; cvta.to.shared.u64 t, %1; cvt.u32.u64 %0, t; }" : "=r"(a) : "l"(p));
    return a;
}
__device__ __forceinline__ void cpasync16(uint32_t s, const void* g) {
    asm volatile("cp.async.cg.shared.global [%0], [%1], 16;" :: "r"(s), "l"(g));
}

// m16n8k8 tf32 MMA, fp32 accumulate. A row-major, B col-major.
__device__ __forceinline__ void mma8(float* c, const uint32_t* a, const uint32_t* b) {
    asm volatile(
        "mma.sync.aligned.m16n8k8.row.col.f32.tf32.tf32.f32 "
        "{%0,%1,%2,%3}, {%4,%5,%6,%7}, {%8,%9}, {%0,%1,%2,%3};\n"
        : "+f"(c[0]), "+f"(c[1]), "+f"(c[2]), "+f"(c[3])
        : "r"(a[0]), "r"(a[1]), "r"(a[2]), "r"(a[3]), "r"(b[0]), "r"(b[1]));
}

// ---------------------------------------------------------------------------
// fused fp32 -> tf32-bits converter for all three operand arrays
// ---------------------------------------------------------------------------
__global__ void conv_all(const float4* __restrict__ i0, uint4* __restrict__ o0, int n0,
                         const float4* __restrict__ i1, uint4* __restrict__ o1, int n1,
                         const float4* __restrict__ i2, uint4* __restrict__ o2, int n2)
{
    const int stride = gridDim.x * blockDim.x;
    const int t0 = blockIdx.x * blockDim.x + threadIdx.x;
    for (int i = t0; i < n0; i += stride) o0[i] = f2t4(i0[i]);
    for (int i = t0; i < n1; i += stride) o1[i] = f2t4(i1[i]);
    for (int i = t0; i < n2; i += stride) o2[i] = f2t4(i2[i]);
}

// ---------------------------------------------------------------------------
// tf32 GEMM on pre-converted bits: C = A*B (+bias).  (R11 config)
// BM=BN=128, BK=16, 256 threads, 8 warps (2m x 4n), warp tile 64x32.
// 4-stage cp.async pipeline, next-stage issue right after the barrier.
// As [m][k] LDA=20, Bs [k][n] LDB=136 (conflict-free fragment access).
// ---------------------------------------------------------------------------
#define LDA 20
#define LDB 136
#define STG_WORDS (128 * LDA + 16 * LDB)          // 4736 words / stage
#define GEMM_SMEM (4 * STG_WORDS * 4)             // 75776 bytes

__global__ __launch_bounds__(256, 2) void gemm_tf32(
    const uint32_t* __restrict__ A, const uint32_t* __restrict__ B,
    const float* __restrict__ bias, uint32_t* __restrict__ C,
    int M, int N, int K, int out_tf32)
{
    extern __shared__ uint32_t sm[];
    const uint32_t sbase = smem_u32(sm);

    const int tid  = threadIdx.x;
    const int lane = tid & 31;
    const int warp = tid >> 5;
    const int row0 = blockIdx.y * 128;
    const int col0 = blockIdx.x * 128;

    const int wm = (warp >> 2) * 64;
    const int wn = (warp & 3) * 32;
    const int r4 = lane >> 2, c4 = lane & 3;

    float acc[4][4][4] = {};

    const int nch = K / 16;

    auto issue = [&](int c, int st) {
        const int kt = c * 16;
        const uint32_t abase = sbase + st * STG_WORDS * 4;
        const uint32_t bbase = abase + 128 * LDA * 4;
        #pragma unroll
        for (int it = 0; it < 2; it++) {
            int idx = tid + it * 256;                 // 0..511
            int m = idx >> 2, k0 = (idx & 3) * 4;
            cpasync16(abase + (m * LDA + k0) * 4,
                      A + (size_t)(row0 + m) * K + kt + k0);
            int kr = idx >> 5, nq = (idx & 31) * 4;
            cpasync16(bbase + (kr * LDB + nq) * 4,
                      B + (size_t)(kt + kr) * N + col0 + nq);
        }
        asm volatile("cp.async.commit_group;" ::: "memory");
    };

    issue(0, 0);
    issue(1, 1);
    issue(2, 2);

    for (int c = 0; c < nch; c++) {
        const int rem = nch - 1 - c;
        if (rem >= 2)      asm volatile("cp.async.wait_group 2;" ::: "memory");
        else if (rem == 1) asm volatile("cp.async.wait_group 1;" ::: "memory");
        else               asm volatile("cp.async.wait_group 0;" ::: "memory");
        __syncthreads();

        // start next stage's loads before compute (stage c+3 reuses buffer
        // (c+3)&3; safe because the barrier above proves stage c-1 is drained)
        if (c + 3 < nch) issue(c + 3, (c + 3) & 3);

        const uint32_t* As = sm + (c & 3) * STG_WORDS;
        const uint32_t* Bs = As + 128 * LDA;

        #pragma unroll
        for (int kk = 0; kk < 2; kk++) {
            const int kc = kk * 8 + c4;
            uint32_t a[4][4], b[4][2];
            #pragma unroll
            for (int fm = 0; fm < 4; fm++) {
                const int r = wm + fm * 16 + r4;
                a[fm][0] = As[r * LDA + kc];
                a[fm][1] = As[(r + 8) * LDA + kc];
                a[fm][2] = As[r * LDA + kc + 4];
                a[fm][3] = As[(r + 8) * LDA + kc + 4];
            }
            #pragma unroll
            for (int fn = 0; fn < 4; fn++) {
                const int n = wn + fn * 8 + r4;
                b[fn][0] = Bs[kc * LDB + n];
                b[fn][1] = Bs[(kc + 4) * LDB + n];
            }
            #pragma unroll
            for (int fm = 0; fm < 4; fm++)
                #pragma unroll
                for (int fn = 0; fn < 4; fn++)
                    mma8(acc[fm][fn], a[fm], b[fn]);
        }
    }

    // Epilogue
    #pragma unroll
    for (int fm = 0; fm < 4; fm++) {
        #pragma unroll
        for (int fn = 0; fn < 4; fn++) {
            const int row = row0 + wm + fm * 16 + r4;
            const int col = col0 + wn + fn * 8 + c4 * 2;
            uint32_t* c0 = C + (size_t)row * N + col;
            uint32_t* c1 = C + (size_t)(row + 8) * N + col;
            if (out_tf32) {
                *(uint2*)c0 = make_uint2(f2t(acc[fm][fn][0]), f2t(acc[fm][fn][1]));
                *(uint2*)c1 = make_uint2(f2t(acc[fm][fn][2]), f2t(acc[fm][fn][3]));
            } else {
                float b0 = 0.f, b1 = 0.f;
                if (bias) { b0 = bias[col]; b1 = bias[col + 1]; }
                *(float2*)c0 = make_float2(acc[fm][fn][0] + b0, acc[fm][fn][1] + b1);
                *(float2*)c1 = make_float2(acc[fm][fn][2] + b0, acc[fm][fn][3] + b1);
            }
        }
    }
}

// ---------------------------------------------------------------------------
// Flash attention (R11 configuration — the measured optimum, ~234us).
// CTA = 128 query rows of one (b,h); 128 threads, 4 warps; warp owns 32 rows
// (2 m-tiles) x 64 cols. Q frags in regs; exp2-domain softmax; swizzled V^T.
// No launch-bounds cap (free register allocation, 2 CTAs/SM).
// ---------------------------------------------------------------------------
#define KVPAD 68
#define ATTN_SMEM ((2 * 64 * KVPAD + 4 * 2048) * 4)   // 67584 bytes

__global__ __launch_bounds__(128) void attn_tf32(
    const uint32_t* __restrict__ qkv, uint32_t* __restrict__ out)
{
    extern __shared__ uint32_t sm[];
    uint32_t* Ksm = sm;                     // [j(64)][KVPAD]
    uint32_t* Vsm = sm + 64 * KVPAD;        // [d(64)][ j ^ 4*((d>>3)&7) ]
    uint32_t* Psm = sm + 2 * 64 * KVPAD;    // per-warp 2048 words

    const int tid  = threadIdx.x;
    const int lane = tid & 31;
    const int warp = tid >> 5;
    const int r4 = lane >> 2, c4 = lane & 3;
    const int qt = blockIdx.x, h = blockIdx.y, b = blockIdx.z;
    const int qr0 = qt * 128 + warp * 32;

    const uint32_t* qbase = qkv + ((size_t)b * SEQ + qr0) * QKV_STRIDE + h * DH;
    const uint32_t* kbase = qkv + (size_t)b * SEQ * QKV_STRIDE + INNER     + h * DH;
    const uint32_t* vbase = qkv + (size_t)b * SEQ * QKV_STRIDE + 2 * INNER + h * DH;

    const float QS = 0.125f * 1.44269504088896340736f;
    uint32_t qf[8][2][4];
    #pragma unroll
    for (int kb = 0; kb < 8; kb++) {
        const int col = kb * 8 + c4;
        #pragma unroll
        for (int m2 = 0; m2 < 2; m2++) {
            const int rb = m2 * 16;
            qf[kb][m2][0] = f2t(__uint_as_float(qbase[(size_t)(rb + r4) * QKV_STRIDE + col]) * QS);
            qf[kb][m2][1] = f2t(__uint_as_float(qbase[(size_t)(rb + r4 + 8) * QKV_STRIDE + col]) * QS);
            qf[kb][m2][2] = f2t(__uint_as_float(qbase[(size_t)(rb + r4) * QKV_STRIDE + col + 4]) * QS);
            qf[kb][m2][3] = f2t(__uint_as_float(qbase[(size_t)(rb + r4 + 8) * QKV_STRIDE + col + 4]) * QS);
        }
    }

    float mrun[2][2] = {{-3.0e38f, -3.0e38f}, {-3.0e38f, -3.0e38f}};
    float lrun[2][2] = {{0.f, 0.f}, {0.f, 0.f}};
    float o[2][8][4] = {};
    uint32_t* Pw = Psm + warp * 2048;

    for (int t = 0; t < 16; t++) {
        __syncthreads();
        const uint32_t* kt_ = kbase + (size_t)t * 64 * QKV_STRIDE;
        const uint32_t* vt_ = vbase + (size_t)t * 64 * QKV_STRIDE;
        #pragma unroll
        for (int it = 0; it < 8; it++) {
            int idx = it * 128 + tid;            // 0..1023 uint4s
            int j = idx >> 4, dq = idx & 15;
            uint4 kv = *(const uint4*)(kt_ + (size_t)j * QKV_STRIDE + dq * 4);
            *(uint4*)&Ksm[j * KVPAD + dq * 4] = kv;
            uint4 vv = *(const uint4*)(vt_ + (size_t)j * QKV_STRIDE + dq * 4);
            const int swc = j ^ (4 * ((dq >> 1) & 7));
            Vsm[(dq * 4 + 0) * KVPAD + swc] = vv.x;
            Vsm[(dq * 4 + 1) * KVPAD + swc] = vv.y;
            Vsm[(dq * 4 + 2) * KVPAD + swc] = vv.z;
            Vsm[(dq * 4 + 3) * KVPAD + swc] = vv.w;
        }
        __syncthreads();

        // ---- S = Q * K^T ----
        float s[2][8][4] = {};
        #pragma unroll
        for (int kb = 0; kb < 8; kb++) {
            #pragma unroll
            for (int fn = 0; fn < 8; fn++) {
                uint32_t bb[2];
                bb[0] = Ksm[(fn * 8 + r4) * KVPAD + kb * 8 + c4];
                bb[1] = Ksm[(fn * 8 + r4) * KVPAD + kb * 8 + c4 + 4];
                mma8(s[0][fn], qf[kb][0], bb);
                mma8(s[1][fn], qf[kb][1], bb);
            }
        }

        // ---- online softmax (exp2 domain) ----
        #pragma unroll
        for (int m2 = 0; m2 < 2; m2++) {
            float mt0 = -3.0e38f, mt1 = -3.0e38f;
            #pragma unroll
            for (int fn = 0; fn < 8; fn++) {
                mt0 = fmaxf(mt0, fmaxf(s[m2][fn][0], s[m2][fn][1]));
                mt1 = fmaxf(mt1, fmaxf(s[m2][fn][2], s[m2][fn][3]));
            }
            mt0 = fmaxf(mt0, __shfl_xor_sync(0xffffffffu, mt0, 1));
            mt0 = fmaxf(mt0, __shfl_xor_sync(0xffffffffu, mt0, 2));
            mt1 = fmaxf(mt1, __shfl_xor_sync(0xffffffffu, mt1, 1));
            mt1 = fmaxf(mt1, __shfl_xor_sync(0xffffffffu, mt1, 2));
            const float mn0 = fmaxf(mrun[m2][0], mt0);
            const float mn1 = fmaxf(mrun[m2][1], mt1);
            const float al0 = ex2(mrun[m2][0] - mn0);
            const float al1 = ex2(mrun[m2][1] - mn1);
            float ls0 = 0.f, ls1 = 0.f;
            #pragma unroll
            for (int fn = 0; fn < 8; fn++) {
                s[m2][fn][0] = ex2(s[m2][fn][0] - mn0); ls0 += s[m2][fn][0];
                s[m2][fn][1] = ex2(s[m2][fn][1] - mn0); ls0 += s[m2][fn][1];
                s[m2][fn][2] = ex2(s[m2][fn][2] - mn1); ls1 += s[m2][fn][2];
                s[m2][fn][3] = ex2(s[m2][fn][3] - mn1); ls1 += s[m2][fn][3];
            }
            ls0 += __shfl_xor_sync(0xffffffffu, ls0, 1);
            ls0 += __shfl_xor_sync(0xffffffffu, ls0, 2);
            ls1 += __shfl_xor_sync(0xffffffffu, ls1, 1);
            ls1 += __shfl_xor_sync(0xffffffffu, ls1, 2);
            lrun[m2][0] = lrun[m2][0] * al0 + ls0;
            lrun[m2][1] = lrun[m2][1] * al1 + ls1;
            mrun[m2][0] = mn0;  mrun[m2][1] = mn1;

            #pragma unroll
            for (int fn = 0; fn < 8; fn++) {
                o[m2][fn][0] *= al0; o[m2][fn][1] *= al0;
                o[m2][fn][2] *= al1; o[m2][fn][3] *= al1;
            }

            const int lp0 = r4 * 4 + 2 * (c4 & 1);
            const int rb  = 2 * (c4 >> 1);
            uint32_t* Pm = Pw + m2 * 1024;
            #pragma unroll
            for (int fn = 0; fn < 8; fn++) {
                Pm[(fn * 4 + rb) * 32 + lp0]         = f2t(s[m2][fn][0]);
                Pm[(fn * 4 + rb) * 32 + lp0 + 1]     = f2t(s[m2][fn][1]);
                Pm[(fn * 4 + rb + 1) * 32 + lp0]     = f2t(s[m2][fn][2]);
                Pm[(fn * 4 + rb + 1) * 32 + lp0 + 1] = f2t(s[m2][fn][3]);
            }
        }
        __syncwarp();

        // ---- O += P * V ----
        #pragma unroll
        for (int kb = 0; kb < 8; kb++) {
            uint32_t a0[4], a1[4];
            #pragma unroll
            for (int r = 0; r < 4; r++) {
                a0[r] = Pw[(kb * 4 + r) * 32 + lane];
                a1[r] = Pw[1024 + (kb * 4 + r) * 32 + lane];
            }
            #pragma unroll
            for (int fn = 0; fn < 8; fn++) {
                const int d = fn * 8 + r4;
                const int sw = 4 * fn;
                uint32_t bb[2];
                bb[0] = Vsm[d * KVPAD + ((kb * 8 + c4) ^ sw)];
                bb[1] = Vsm[d * KVPAD + ((kb * 8 + c4 + 4) ^ sw)];
                mma8(o[0][fn], a0, bb);
                mma8(o[1][fn], a1, bb);
            }
        }
        __syncwarp();
    }

    // ---- normalize, emit tf32 bits for GEMM2 ----
    #pragma unroll
    for (int m2 = 0; m2 < 2; m2++) {
        const float inv0 = 1.f / lrun[m2][0];
        const float inv1 = 1.f / lrun[m2][1];
        uint32_t* ob = out + ((size_t)b * SEQ + qr0 + m2 * 16) * INNER + h * DH;
        #pragma unroll
        for (int fn = 0; fn < 8; fn++) {
            const int col = fn * 8 + 2 * c4;
            *(uint2*)&ob[(size_t)r4 * INNER + col] =
                make_uint2(f2t(o[m2][fn][0] * inv0), f2t(o[m2][fn][1] * inv0));
            *(uint2*)&ob[(size_t)(r4 + 8) * INNER + col] =
                make_uint2(f2t(o[m2][fn][2] * inv1), f2t(o[m2][fn][3] * inv1));
        }
    }
}

// ---------------------------------------------------------------------------
// Launch
// ---------------------------------------------------------------------------
extern "C" void kernel_launch(void* const* d_in, const int* in_sizes, int n_in,
                              void* d_out, int out_size)
{
    const float* x      = (const float*)d_in[0];
    const float* w_qkv  = (const float*)d_in[1];
    const float* w_out  = (const float*)d_in[2];
    const float* b_out  = (const float*)d_in[3];
    uint32_t* out = (uint32_t*)d_out;

    uint32_t *qkv, *att, *xt, *wqkvt, *woutt;
    cudaGetSymbolAddress((void**)&qkv,   g_qkv);
    cudaGetSymbolAddress((void**)&att,   g_att);
    cudaGetSymbolAddress((void**)&xt,    g_xt);
    cudaGetSymbolAddress((void**)&wqkvt, g_wqkvt);
    cudaGetSymbolAddress((void**)&woutt, g_woutt);

    const int M = BATCH * SEQ;   // 8192

    cudaFuncSetAttribute(gemm_tf32, cudaFuncAttributeMaxDynamicSharedMemorySize, GEMM_SMEM);
    cudaFuncSetAttribute(attn_tf32, cudaFuncAttributeMaxDynamicSharedMemorySize, ATTN_SMEM);

    // 0) pre-convert all operands to tf32 bits (single fused launch)
    conv_all<<<2048, 256>>>(
        (const float4*)x,     (uint4*)xt,    (int)((size_t)M * DIM / 4),
        (const float4*)w_qkv, (uint4*)wqkvt, (int)((size_t)DIM * 3 * INNER / 4),
        (const float4*)w_out, (uint4*)woutt, (int)((size_t)INNER * DIM / 4));

    // 1) QKV projection (emits tf32 bits)
    gemm_tf32<<<dim3(3 * INNER / 128, M / 128), 256, GEMM_SMEM>>>(
        xt, wqkvt, nullptr, qkv, M, 3 * INNER, DIM, 1);

    // 2) Flash attention (emits tf32 bits)
    attn_tf32<<<dim3(SEQ / 128, HEADS, BATCH), 128, ATTN_SMEM>>>(qkv, att);

    // 3) Output projection (fp32 + bias, final)
    gemm_tf32<<<dim3(DIM / 128, M / 128), 256, GEMM_SMEM>>>(
        att, woutt, b_out, out, M, DIM, INNER, 0);
}

// round 15
// speedup vs baseline: 1.1501x; 1.1211x over previous
#include <cuda_runtime.h>
#include <cstdint>

#define BATCH 8
#define SEQ   1024
#define DIM   1024
#define HEADS 16
#define DH    64
#define INNER 1024
#define QKV_STRIDE (3 * INNER)

// Scratch (static device arrays: the sanctioned no-alloc workaround)
__device__ uint32_t g_qkv[(size_t)BATCH * SEQ * 3 * INNER];   // tf32 bits
__device__ uint32_t g_att[(size_t)BATCH * SEQ * INNER];       // tf32 bits
__device__ uint32_t g_xt[(size_t)BATCH * SEQ * DIM];          // x as tf32 bits
__device__ uint32_t g_wqkvt[(size_t)DIM * 3 * INNER];         // w_qkv as tf32 bits
__device__ uint32_t g_woutt[(size_t)INNER * DIM];             // w_out as tf32 bits

// ---------------------------------------------------------------------------
// helpers
// ---------------------------------------------------------------------------
__device__ __forceinline__ uint32_t f2t(float x) {
    uint32_t r;
    asm("cvt.rna.tf32.f32 %0, %1;" : "=r"(r) : "f"(x));
    return r;
}
__device__ __forceinline__ uint4 f2t4(float4 v) {
    return make_uint4(f2t(v.x), f2t(v.y), f2t(v.z), f2t(v.w));
}
__device__ __forceinline__ float ex2(float x) {
    float r;
    asm("ex2.approx.ftz.f32 %0, %1;" : "=f"(r) : "f"(x));
    return r;
}
__device__ __forceinline__ uint32_t smem_u32(const void* p) {
    uint32_t a;
    asm("{ .reg .u64 t; cvta.to.shared.u64 t, %1; cvt.u32.u64 %0, t; }" : "=r"(a) : "l"(p));
    return a;
}
__device__ __forceinline__ void cpasync16(uint32_t s, const void* g) {
    asm volatile("cp.async.cg.shared.global [%0], [%1], 16;" :: "r"(s), "l"(g));
}

// m16n8k8 tf32 MMA, fp32 accumulate. A row-major, B col-major.
__device__ __forceinline__ void mma8(float* c, const uint32_t* a, const uint32_t* b) {
    asm volatile(
        "mma.sync.aligned.m16n8k8.row.col.f32.tf32.tf32.f32 "
        "{%0,%1,%2,%3}, {%4,%5,%6,%7}, {%8,%9}, {%0,%1,%2,%3};\n"
        : "+f"(c[0]), "+f"(c[1]), "+f"(c[2]), "+f"(c[3])
        : "r"(a[0]), "r"(a[1]), "r"(a[2]), "r"(a[3]), "r"(b[0]), "r"(b[1]));
}

// ---------------------------------------------------------------------------
// fused fp32 -> tf32-bits converter for all three operand arrays
// ---------------------------------------------------------------------------
__global__ void conv_all(const float4* __restrict__ i0, uint4* __restrict__ o0, int n0,
                         const float4* __restrict__ i1, uint4* __restrict__ o1, int n1,
                         const float4* __restrict__ i2, uint4* __restrict__ o2, int n2)
{
    const int stride = gridDim.x * blockDim.x;
    const int t0 = blockIdx.x * blockDim.x + threadIdx.x;
    for (int i = t0; i < n0; i += stride) o0[i] = f2t4(i0[i]);
    for (int i = t0; i < n1; i += stride) o1[i] = f2t4(i1[i]);
    for (int i = t0; i < n2; i += stride) o2[i] = f2t4(i2[i]);
}

// ---------------------------------------------------------------------------
// tf32 GEMM on pre-converted bits: C = A*B (+bias).
// BM=BN=128, BK=16, 128 threads, 4 warps (2m x 2n), warp tile 64x64
// (4m x 8n m16n8k8 frags -> 1.0 LDS per MMA, halved crossbar pressure).
// 4-stage cp.async pipeline, next-stage issue AFTER the MMA block (R11
// ordering — issue-early measured slower in R14).
// As [m][k] LDA=20, Bs [k][n] LDB=136 (conflict-free fragment access).
// ---------------------------------------------------------------------------
#define LDA 20
#define LDB 136
#define STG_WORDS (128 * LDA + 16 * LDB)          // 4736 words / stage
#define GEMM_SMEM (4 * STG_WORDS * 4)             // 75776 bytes

__global__ __launch_bounds__(128) void gemm_tf32(
    const uint32_t* __restrict__ A, const uint32_t* __restrict__ B,
    const float* __restrict__ bias, uint32_t* __restrict__ C,
    int M, int N, int K, int out_tf32)
{
    extern __shared__ uint32_t sm[];
    const uint32_t sbase = smem_u32(sm);

    const int tid  = threadIdx.x;
    const int lane = tid & 31;
    const int warp = tid >> 5;
    const int row0 = blockIdx.y * 128;
    const int col0 = blockIdx.x * 128;

    const int wm = (warp >> 1) * 64;
    const int wn = (warp & 1) * 64;
    const int r4 = lane >> 2, c4 = lane & 3;

    float acc[4][8][4] = {};

    const int nch = K / 16;

    auto issue = [&](int c, int st) {
        const int kt = c * 16;
        const uint32_t abase = sbase + st * STG_WORDS * 4;
        const uint32_t bbase = abase + 128 * LDA * 4;
        #pragma unroll
        for (int it = 0; it < 4; it++) {
            int idx = tid + it * 128;                 // 0..511
            int m = idx >> 2, k0 = (idx & 3) * 4;
            cpasync16(abase + (m * LDA + k0) * 4,
                      A + (size_t)(row0 + m) * K + kt + k0);
            int kr = idx >> 5, nq = (idx & 31) * 4;
            cpasync16(bbase + (kr * LDB + nq) * 4,
                      B + (size_t)(kt + kr) * N + col0 + nq);
        }
        asm volatile("cp.async.commit_group;" ::: "memory");
    };

    issue(0, 0);
    issue(1, 1);
    issue(2, 2);

    for (int c = 0; c < nch; c++) {
        const int rem = nch - 1 - c;
        if (rem >= 2)      asm volatile("cp.async.wait_group 2;" ::: "memory");
        else if (rem == 1) asm volatile("cp.async.wait_group 1;" ::: "memory");
        else               asm volatile("cp.async.wait_group 0;" ::: "memory");
        __syncthreads();

        const uint32_t* As = sm + (c & 3) * STG_WORDS;
        const uint32_t* Bs = As + 128 * LDA;

        #pragma unroll
        for (int kk = 0; kk < 2; kk++) {
            const int kc = kk * 8 + c4;
            uint32_t a[4][4], b[8][2];
            #pragma unroll
            for (int fm = 0; fm < 4; fm++) {
                const int r = wm + fm * 16 + r4;
                a[fm][0] = As[r * LDA + kc];
                a[fm][1] = As[(r + 8) * LDA + kc];
                a[fm][2] = As[r * LDA + kc + 4];
                a[fm][3] = As[(r + 8) * LDA + kc + 4];
            }
            #pragma unroll
            for (int fn = 0; fn < 8; fn++) {
                const int n = wn + fn * 8 + r4;
                b[fn][0] = Bs[kc * LDB + n];
                b[fn][1] = Bs[(kc + 4) * LDB + n];
            }
            #pragma unroll
            for (int fm = 0; fm < 4; fm++)
                #pragma unroll
                for (int fn = 0; fn < 8; fn++)
                    mma8(acc[fm][fn], a[fm], b[fn]);
        }

        if (c + 3 < nch) issue(c + 3, (c + 3) & 3);
    }

    // Epilogue
    #pragma unroll
    for (int fm = 0; fm < 4; fm++) {
        #pragma unroll
        for (int fn = 0; fn < 8; fn++) {
            const int row = row0 + wm + fm * 16 + r4;
            const int col = col0 + wn + fn * 8 + c4 * 2;
            uint32_t* c0 = C + (size_t)row * N + col;
            uint32_t* c1 = C + (size_t)(row + 8) * N + col;
            if (out_tf32) {
                *(uint2*)c0 = make_uint2(f2t(acc[fm][fn][0]), f2t(acc[fm][fn][1]));
                *(uint2*)c1 = make_uint2(f2t(acc[fm][fn][2]), f2t(acc[fm][fn][3]));
            } else {
                float b0 = 0.f, b1 = 0.f;
                if (bias) { b0 = bias[col]; b1 = bias[col + 1]; }
                *(float2*)c0 = make_float2(acc[fm][fn][0] + b0, acc[fm][fn][1] + b1);
                *(float2*)c1 = make_float2(acc[fm][fn][2] + b0, acc[fm][fn][3] + b1);
            }
        }
    }
}

// ---------------------------------------------------------------------------
// Flash attention (R11 configuration — the measured optimum, ~234us).
// CTA = 128 query rows of one (b,h); 128 threads, 4 warps; warp owns 32 rows
// (2 m-tiles) x 64 cols. Q frags in regs; exp2-domain softmax; swizzled V^T.
// No launch-bounds cap (free register allocation, 2 CTAs/SM).
// ---------------------------------------------------------------------------
#define KVPAD 68
#define ATTN_SMEM ((2 * 64 * KVPAD + 4 * 2048) * 4)   // 67584 bytes

__global__ __launch_bounds__(128) void attn_tf32(
    const uint32_t* __restrict__ qkv, uint32_t* __restrict__ out)
{
    extern __shared__ uint32_t sm[];
    uint32_t* Ksm = sm;                     // [j(64)][KVPAD]
    uint32_t* Vsm = sm + 64 * KVPAD;        // [d(64)][ j ^ 4*((d>>3)&7) ]
    uint32_t* Psm = sm + 2 * 64 * KVPAD;    // per-warp 2048 words

    const int tid  = threadIdx.x;
    const int lane = tid & 31;
    const int warp = tid >> 5;
    const int r4 = lane >> 2, c4 = lane & 3;
    const int qt = blockIdx.x, h = blockIdx.y, b = blockIdx.z;
    const int qr0 = qt * 128 + warp * 32;

    const uint32_t* qbase = qkv + ((size_t)b * SEQ + qr0) * QKV_STRIDE + h * DH;
    const uint32_t* kbase = qkv + (size_t)b * SEQ * QKV_STRIDE + INNER     + h * DH;
    const uint32_t* vbase = qkv + (size_t)b * SEQ * QKV_STRIDE + 2 * INNER + h * DH;

    const float QS = 0.125f * 1.44269504088896340736f;
    uint32_t qf[8][2][4];
    #pragma unroll
    for (int kb = 0; kb < 8; kb++) {
        const int col = kb * 8 + c4;
        #pragma unroll
        for (int m2 = 0; m2 < 2; m2++) {
            const int rb = m2 * 16;
            qf[kb][m2][0] = f2t(__uint_as_float(qbase[(size_t)(rb + r4) * QKV_STRIDE + col]) * QS);
            qf[kb][m2][1] = f2t(__uint_as_float(qbase[(size_t)(rb + r4 + 8) * QKV_STRIDE + col]) * QS);
            qf[kb][m2][2] = f2t(__uint_as_float(qbase[(size_t)(rb + r4) * QKV_STRIDE + col + 4]) * QS);
            qf[kb][m2][3] = f2t(__uint_as_float(qbase[(size_t)(rb + r4 + 8) * QKV_STRIDE + col + 4]) * QS);
        }
    }

    float mrun[2][2] = {{-3.0e38f, -3.0e38f}, {-3.0e38f, -3.0e38f}};
    float lrun[2][2] = {{0.f, 0.f}, {0.f, 0.f}};
    float o[2][8][4] = {};
    uint32_t* Pw = Psm + warp * 2048;

    for (int t = 0; t < 16; t++) {
        __syncthreads();
        const uint32_t* kt_ = kbase + (size_t)t * 64 * QKV_STRIDE;
        const uint32_t* vt_ = vbase + (size_t)t * 64 * QKV_STRIDE;
        #pragma unroll
        for (int it = 0; it < 8; it++) {
            int idx = it * 128 + tid;            // 0..1023 uint4s
            int j = idx >> 4, dq = idx & 15;
            uint4 kv = *(const uint4*)(kt_ + (size_t)j * QKV_STRIDE + dq * 4);
            *(uint4*)&Ksm[j * KVPAD + dq * 4] = kv;
            uint4 vv = *(const uint4*)(vt_ + (size_t)j * QKV_STRIDE + dq * 4);
            const int swc = j ^ (4 * ((dq >> 1) & 7));
            Vsm[(dq * 4 + 0) * KVPAD + swc] = vv.x;
            Vsm[(dq * 4 + 1) * KVPAD + swc] = vv.y;
            Vsm[(dq * 4 + 2) * KVPAD + swc] = vv.z;
            Vsm[(dq * 4 + 3) * KVPAD + swc] = vv.w;
        }
        __syncthreads();

        // ---- S = Q * K^T ----
        float s[2][8][4] = {};
        #pragma unroll
        for (int kb = 0; kb < 8; kb++) {
            #pragma unroll
            for (int fn = 0; fn < 8; fn++) {
                uint32_t bb[2];
                bb[0] = Ksm[(fn * 8 + r4) * KVPAD + kb * 8 + c4];
                bb[1] = Ksm[(fn * 8 + r4) * KVPAD + kb * 8 + c4 + 4];
                mma8(s[0][fn], qf[kb][0], bb);
                mma8(s[1][fn], qf[kb][1], bb);
            }
        }

        // ---- online softmax (exp2 domain) ----
        #pragma unroll
        for (int m2 = 0; m2 < 2; m2++) {
            float mt0 = -3.0e38f, mt1 = -3.0e38f;
            #pragma unroll
            for (int fn = 0; fn < 8; fn++) {
                mt0 = fmaxf(mt0, fmaxf(s[m2][fn][0], s[m2][fn][1]));
                mt1 = fmaxf(mt1, fmaxf(s[m2][fn][2], s[m2][fn][3]));
            }
            mt0 = fmaxf(mt0, __shfl_xor_sync(0xffffffffu, mt0, 1));
            mt0 = fmaxf(mt0, __shfl_xor_sync(0xffffffffu, mt0, 2));
            mt1 = fmaxf(mt1, __shfl_xor_sync(0xffffffffu, mt1, 1));
            mt1 = fmaxf(mt1, __shfl_xor_sync(0xffffffffu, mt1, 2));
            const float mn0 = fmaxf(mrun[m2][0], mt0);
            const float mn1 = fmaxf(mrun[m2][1], mt1);
            const float al0 = ex2(mrun[m2][0] - mn0);
            const float al1 = ex2(mrun[m2][1] - mn1);
            float ls0 = 0.f, ls1 = 0.f;
            #pragma unroll
            for (int fn = 0; fn < 8; fn++) {
                s[m2][fn][0] = ex2(s[m2][fn][0] - mn0); ls0 += s[m2][fn][0];
                s[m2][fn][1] = ex2(s[m2][fn][1] - mn0); ls0 += s[m2][fn][1];
                s[m2][fn][2] = ex2(s[m2][fn][2] - mn1); ls1 += s[m2][fn][2];
                s[m2][fn][3] = ex2(s[m2][fn][3] - mn1); ls1 += s[m2][fn][3];
            }
            ls0 += __shfl_xor_sync(0xffffffffu, ls0, 1);
            ls0 += __shfl_xor_sync(0xffffffffu, ls0, 2);
            ls1 += __shfl_xor_sync(0xffffffffu, ls1, 1);
            ls1 += __shfl_xor_sync(0xffffffffu, ls1, 2);
            lrun[m2][0] = lrun[m2][0] * al0 + ls0;
            lrun[m2][1] = lrun[m2][1] * al1 + ls1;
            mrun[m2][0] = mn0;  mrun[m2][1] = mn1;

            #pragma unroll
            for (int fn = 0; fn < 8; fn++) {
                o[m2][fn][0] *= al0; o[m2][fn][1] *= al0;
                o[m2][fn][2] *= al1; o[m2][fn][3] *= al1;
            }

            const int lp0 = r4 * 4 + 2 * (c4 & 1);
            const int rb  = 2 * (c4 >> 1);
            uint32_t* Pm = Pw + m2 * 1024;
            #pragma unroll
            for (int fn = 0; fn < 8; fn++) {
                Pm[(fn * 4 + rb) * 32 + lp0]         = f2t(s[m2][fn][0]);
                Pm[(fn * 4 + rb) * 32 + lp0 + 1]     = f2t(s[m2][fn][1]);
                Pm[(fn * 4 + rb + 1) * 32 + lp0]     = f2t(s[m2][fn][2]);
                Pm[(fn * 4 + rb + 1) * 32 + lp0 + 1] = f2t(s[m2][fn][3]);
            }
        }
        __syncwarp();

        // ---- O += P * V ----
        #pragma unroll
        for (int kb = 0; kb < 8; kb++) {
            uint32_t a0[4], a1[4];
            #pragma unroll
            for (int r = 0; r < 4; r++) {
                a0[r] = Pw[(kb * 4 + r) * 32 + lane];
                a1[r] = Pw[1024 + (kb * 4 + r) * 32 + lane];
            }
            #pragma unroll
            for (int fn = 0; fn < 8; fn++) {
                const int d = fn * 8 + r4;
                const int sw = 4 * fn;
                uint32_t bb[2];
                bb[0] = Vsm[d * KVPAD + ((kb * 8 + c4) ^ sw)];
                bb[1] = Vsm[d * KVPAD + ((kb * 8 + c4 + 4) ^ sw)];
                mma8(o[0][fn], a0, bb);
                mma8(o[1][fn], a1, bb);
            }
        }
        __syncwarp();
    }

    // ---- normalize, emit tf32 bits for GEMM2 ----
    #pragma unroll
    for (int m2 = 0; m2 < 2; m2++) {
        const float inv0 = 1.f / lrun[m2][0];
        const float inv1 = 1.f / lrun[m2][1];
        uint32_t* ob = out + ((size_t)b * SEQ + qr0 + m2 * 16) * INNER + h * DH;
        #pragma unroll
        for (int fn = 0; fn < 8; fn++) {
            const int col = fn * 8 + 2 * c4;
            *(uint2*)&ob[(size_t)r4 * INNER + col] =
                make_uint2(f2t(o[m2][fn][0] * inv0), f2t(o[m2][fn][1] * inv0));
            *(uint2*)&ob[(size_t)(r4 + 8) * INNER + col] =
                make_uint2(f2t(o[m2][fn][2] * inv1), f2t(o[m2][fn][3] * inv1));
        }
    }
}

// ---------------------------------------------------------------------------
// Launch
// ---------------------------------------------------------------------------
extern "C" void kernel_launch(void* const* d_in, const int* in_sizes, int n_in,
                              void* d_out, int out_size)
{
    const float* x      = (const float*)d_in[0];
    const float* w_qkv  = (const float*)d_in[1];
    const float* w_out  = (const float*)d_in[2];
    const float* b_out  = (const float*)d_in[3];
    uint32_t* out = (uint32_t*)d_out;

    uint32_t *qkv, *att, *xt, *wqkvt, *woutt;
    cudaGetSymbolAddress((void**)&qkv,   g_qkv);
    cudaGetSymbolAddress((void**)&att,   g_att);
    cudaGetSymbolAddress((void**)&xt,    g_xt);
    cudaGetSymbolAddress((void**)&wqkvt, g_wqkvt);
    cudaGetSymbolAddress((void**)&woutt, g_woutt);

    const int M = BATCH * SEQ;   // 8192

    cudaFuncSetAttribute(gemm_tf32, cudaFuncAttributeMaxDynamicSharedMemorySize, GEMM_SMEM);
    cudaFuncSetAttribute(attn_tf32, cudaFuncAttributeMaxDynamicSharedMemorySize, ATTN_SMEM);

    // 0) pre-convert all operands to tf32 bits (single fused launch)
    conv_all<<<2048, 256>>>(
        (const float4*)x,     (uint4*)xt,    (int)((size_t)M * DIM / 4),
        (const float4*)w_qkv, (uint4*)wqkvt, (int)((size_t)DIM * 3 * INNER / 4),
        (const float4*)w_out, (uint4*)woutt, (int)((size_t)INNER * DIM / 4));

    // 1) QKV projection (emits tf32 bits)
    gemm_tf32<<<dim3(3 * INNER / 128, M / 128), 128, GEMM_SMEM>>>(
        xt, wqkvt, nullptr, qkv, M, 3 * INNER, DIM, 1);

    // 2) Flash attention (emits tf32 bits)
    attn_tf32<<<dim3(SEQ / 128, HEADS, BATCH), 128, ATTN_SMEM>>>(qkv, att);

    // 3) Output projection (fp32 + bias, final)
    gemm_tf32<<<dim3(DIM / 128, M / 128), 128, GEMM_SMEM>>>(
        att, woutt, b_out, out, M, DIM, INNER, 0);
}

// round 16
// speedup vs baseline: 1.2191x; 1.0600x over previous
#include <cuda_runtime.h>
#include <cstdint>

#define BATCH 8
#define SEQ   1024
#define DIM   1024
#define HEADS 16
#define DH    64
#define INNER 1024
#define QKV_STRIDE (3 * INNER)

// Scratch (static device arrays: the sanctioned no-alloc workaround)
__device__ uint32_t g_qkv[(size_t)BATCH * SEQ * 3 * INNER];   // tf32 bits (Q,K used; V unused)
__device__ uint32_t g_vt[(size_t)BATCH * HEADS * DH * SEQ];   // V transposed: [b,h][d][j], tf32 bits
__device__ uint32_t g_att[(size_t)BATCH * SEQ * INNER];       // tf32 bits
__device__ uint32_t g_xt[(size_t)BATCH * SEQ * DIM];          // x as tf32 bits
__device__ uint32_t g_wqkvt[(size_t)DIM * 3 * INNER];         // w_qkv as tf32 bits
__device__ uint32_t g_woutt[(size_t)INNER * DIM];             // w_out as tf32 bits

// ---------------------------------------------------------------------------
// helpers
// ---------------------------------------------------------------------------
__device__ __forceinline__ uint32_t f2t(float x) {
    uint32_t r;
    asm("cvt.rna.tf32.f32 %0, %1;" : "=r"(r) : "f"(x));
    return r;
}
__device__ __forceinline__ uint4 f2t4(float4 v) {
    return make_uint4(f2t(v.x), f2t(v.y), f2t(v.z), f2t(v.w));
}
__device__ __forceinline__ float ex2(float x) {
    float r;
    asm("ex2.approx.ftz.f32 %0, %1;" : "=f"(r) : "f"(x));
    return r;
}
__device__ __forceinline__ uint32_t smem_u32(const void* p) {
    uint32_t a;
    asm("{ .reg .u64 t; cvta.to.shared.u64 t, %1; cvt.u32.u64 %0, t; }" : "=r"(a) : "l"(p));
    return a;
}
__device__ __forceinline__ void cpasync16(uint32_t s, const void* g) {
    asm volatile("cp.async.cg.shared.global [%0], [%1], 16;" :: "r"(s), "l"(g));
}

// m16n8k8 tf32 MMA, fp32 accumulate. A row-major, B col-major.
__device__ __forceinline__ void mma8(float* c, const uint32_t* a, const uint32_t* b) {
    asm volatile(
        "mma.sync.aligned.m16n8k8.row.col.f32.tf32.tf32.f32 "
        "{%0,%1,%2,%3}, {%4,%5,%6,%7}, {%8,%9}, {%0,%1,%2,%3};\n"
        : "+f"(c[0]), "+f"(c[1]), "+f"(c[2]), "+f"(c[3])
        : "r"(a[0]), "r"(a[1]), "r"(a[2]), "r"(a[3]), "r"(b[0]), "r"(b[1]));
}

// ---------------------------------------------------------------------------
// fused fp32 -> tf32-bits converter for all three operand arrays
// ---------------------------------------------------------------------------
__global__ void conv_all(const float4* __restrict__ i0, uint4* __restrict__ o0, int n0,
                         const float4* __restrict__ i1, uint4* __restrict__ o1, int n1,
                         const float4* __restrict__ i2, uint4* __restrict__ o2, int n2)
{
    const int stride = gridDim.x * blockDim.x;
    const int t0 = blockIdx.x * blockDim.x + threadIdx.x;
    for (int i = t0; i < n0; i += stride) o0[i] = f2t4(i0[i]);
    for (int i = t0; i < n1; i += stride) o1[i] = f2t4(i1[i]);
    for (int i = t0; i < n2; i += stride) o2[i] = f2t4(i2[i]);
}

// ---------------------------------------------------------------------------
// tf32 GEMM on pre-converted bits: C = A*B (+bias).
// BM=BN=128, BK=16, 128 threads, 4 warps (2m x 2n), warp tile 64x64.
// 4-stage cp.async pipeline, next-stage issue AFTER the MMA block.
// mode 0: fp32 + bias epilogue.  mode 1 (qkv): tf32-bit epilogue; CTAs in the
// V column range (col0 >= 2048) scatter into vt[b,h][d][j] (transposed).
// ---------------------------------------------------------------------------
#define LDA 20
#define LDB 136
#define STG_WORDS (128 * LDA + 16 * LDB)          // 4736 words / stage
#define GEMM_SMEM (4 * STG_WORDS * 4)             // 75776 bytes

__global__ __launch_bounds__(128) void gemm_tf32(
    const uint32_t* __restrict__ A, const uint32_t* __restrict__ B,
    const float* __restrict__ bias, uint32_t* __restrict__ C,
    uint32_t* __restrict__ vt,
    int M, int N, int K, int mode)
{
    extern __shared__ uint32_t sm[];
    const uint32_t sbase = smem_u32(sm);

    const int tid  = threadIdx.x;
    const int lane = tid & 31;
    const int warp = tid >> 5;
    const int row0 = blockIdx.y * 128;
    const int col0 = blockIdx.x * 128;

    const int wm = (warp >> 1) * 64;
    const int wn = (warp & 1) * 64;
    const int r4 = lane >> 2, c4 = lane & 3;

    float acc[4][8][4] = {};

    const int nch = K / 16;

    auto issue = [&](int c, int st) {
        const int kt = c * 16;
        const uint32_t abase = sbase + st * STG_WORDS * 4;
        const uint32_t bbase = abase + 128 * LDA * 4;
        #pragma unroll
        for (int it = 0; it < 4; it++) {
            int idx = tid + it * 128;                 // 0..511
            int m = idx >> 2, k0 = (idx & 3) * 4;
            cpasync16(abase + (m * LDA + k0) * 4,
                      A + (size_t)(row0 + m) * K + kt + k0);
            int kr = idx >> 5, nq = (idx & 31) * 4;
            cpasync16(bbase + (kr * LDB + nq) * 4,
                      B + (size_t)(kt + kr) * N + col0 + nq);
        }
        asm volatile("cp.async.commit_group;" ::: "memory");
    };

    issue(0, 0);
    issue(1, 1);
    issue(2, 2);

    for (int c = 0; c < nch; c++) {
        const int rem = nch - 1 - c;
        if (rem >= 2)      asm volatile("cp.async.wait_group 2;" ::: "memory");
        else if (rem == 1) asm volatile("cp.async.wait_group 1;" ::: "memory");
        else               asm volatile("cp.async.wait_group 0;" ::: "memory");
        __syncthreads();

        const uint32_t* As = sm + (c & 3) * STG_WORDS;
        const uint32_t* Bs = As + 128 * LDA;

        #pragma unroll
        for (int kk = 0; kk < 2; kk++) {
            const int kc = kk * 8 + c4;
            uint32_t a[4][4], b[8][2];
            #pragma unroll
            for (int fm = 0; fm < 4; fm++) {
                const int r = wm + fm * 16 + r4;
                a[fm][0] = As[r * LDA + kc];
                a[fm][1] = As[(r + 8) * LDA + kc];
                a[fm][2] = As[r * LDA + kc + 4];
                a[fm][3] = As[(r + 8) * LDA + kc + 4];
            }
            #pragma unroll
            for (int fn = 0; fn < 8; fn++) {
                const int n = wn + fn * 8 + r4;
                b[fn][0] = Bs[kc * LDB + n];
                b[fn][1] = Bs[(kc + 4) * LDB + n];
            }
            #pragma unroll
            for (int fm = 0; fm < 4; fm++)
                #pragma unroll
                for (int fn = 0; fn < 8; fn++)
                    mma8(acc[fm][fn], a[fm], b[fn]);
        }

        if (c + 3 < nch) issue(c + 3, (c + 3) & 3);
    }

    // Epilogue
    if (mode == 1 && col0 >= 2048) {
        // V third: scatter tf32 bits into vt[((b*16+h)*64+d)*1024 + j]
        #pragma unroll
        for (int fm = 0; fm < 4; fm++) {
            #pragma unroll
            for (int fn = 0; fn < 8; fn++) {
                const int inner = col0 - 2048 + wn + fn * 8 + c4 * 2;  // h*64+d
                const int h = inner >> 6, d = inner & 63;
                #pragma unroll
                for (int rr = 0; rr < 2; rr++) {
                    const int row = row0 + wm + fm * 16 + r4 + rr * 8;
                    const int bidx = row >> 10, j = row & 1023;
                    uint32_t* vbase = vt + (((size_t)(bidx * HEADS + h) * DH + d) << 10) + j;
                    vbase[0]    = f2t(acc[fm][fn][rr * 2 + 0]);
                    vbase[1024] = f2t(acc[fm][fn][rr * 2 + 1]);   // d+1 row
                }
            }
        }
    } else {
        #pragma unroll
        for (int fm = 0; fm < 4; fm++) {
            #pragma unroll
            for (int fn = 0; fn < 8; fn++) {
                const int row = row0 + wm + fm * 16 + r4;
                const int col = col0 + wn + fn * 8 + c4 * 2;
                uint32_t* c0 = C + (size_t)row * N + col;
                uint32_t* c1 = C + (size_t)(row + 8) * N + col;
                if (mode == 1) {
                    *(uint2*)c0 = make_uint2(f2t(acc[fm][fn][0]), f2t(acc[fm][fn][1]));
                    *(uint2*)c1 = make_uint2(f2t(acc[fm][fn][2]), f2t(acc[fm][fn][3]));
                } else {
                    float b0 = 0.f, b1 = 0.f;
                    if (bias) { b0 = bias[col]; b1 = bias[col + 1]; }
                    *(float2*)c0 = make_float2(acc[fm][fn][0] + b0, acc[fm][fn][1] + b1);
                    *(float2*)c1 = make_float2(acc[fm][fn][2] + b0, acc[fm][fn][3] + b1);
                }
            }
        }
    }
}

// ---------------------------------------------------------------------------
// Flash attention. CTA = 128 query rows of one (b,h); 128 threads, 4 warps;
// warp owns 32 rows (2 m-tiles) x 64 cols. Q frags in regs; exp2 softmax.
// K and V^T (pre-transposed by GEMM1) both cp.async double-buffered; prefetch
// of tile t+1 issued after the S-MMA block. Plain PAD=68 rows (conflict-free).
// smem: K[2]+V[2] 4*4352 + P 8192 = 25600 words = 100 KB -> 2 CTAs/SM.
// ---------------------------------------------------------------------------
#define KVPAD 68
#define KVBUF (64 * KVPAD)                     // 4352 words
#define ATTN_SMEM ((4 * KVBUF + 4 * 2048) * 4) // 102400 bytes

__global__ __launch_bounds__(128) void attn_tf32(
    const uint32_t* __restrict__ qkv, const uint32_t* __restrict__ vt,
    uint32_t* __restrict__ out)
{
    extern __shared__ uint32_t sm[];
    uint32_t* Psm = sm + 4 * KVBUF;          // per-warp 2048 words
    const uint32_t sbase = smem_u32(sm);

    const int tid  = threadIdx.x;
    const int lane = tid & 31;
    const int warp = tid >> 5;
    const int r4 = lane >> 2, c4 = lane & 3;
    const int qt = blockIdx.x, h = blockIdx.y, b = blockIdx.z;
    const int qr0 = qt * 128 + warp * 32;

    const uint32_t* qbase = qkv + ((size_t)b * SEQ + qr0) * QKV_STRIDE + h * DH;
    const uint32_t* kbase = qkv + (size_t)b * SEQ * QKV_STRIDE + INNER + h * DH;
    const uint32_t* vhead = vt + ((size_t)(b * HEADS + h) * DH) * SEQ;

    // prefetch tile t into buffer s (K: [j][d], V^T: [d][j], both plain rows)
    auto issueKV = [&](int t, int s) {
        const uint32_t kdst = sbase + (s * KVBUF) * 4;
        const uint32_t vdst = sbase + ((2 + s) * KVBUF) * 4;
        const uint32_t* kt_ = kbase + (size_t)t * 64 * QKV_STRIDE;
        const uint32_t* vt_ = vhead + t * 64;
        #pragma unroll
        for (int it = 0; it < 8; it++) {
            int idx = it * 128 + tid;            // 0..1023
            int r = idx >> 4, q = idx & 15;      // row, 16B segment
            cpasync16(kdst + (r * KVPAD + q * 4) * 4,
                      kt_ + (size_t)r * QKV_STRIDE + q * 4);
            cpasync16(vdst + (r * KVPAD + q * 4) * 4,
                      vt_ + (size_t)r * SEQ + q * 4);
        }
        asm volatile("cp.async.commit_group;" ::: "memory");
    };

    const float QS = 0.125f * 1.44269504088896340736f;
    uint32_t qf[8][2][4];
    #pragma unroll
    for (int kb = 0; kb < 8; kb++) {
        const int col = kb * 8 + c4;
        #pragma unroll
        for (int m2 = 0; m2 < 2; m2++) {
            const int rb = m2 * 16;
            qf[kb][m2][0] = f2t(__uint_as_float(qbase[(size_t)(rb + r4) * QKV_STRIDE + col]) * QS);
            qf[kb][m2][1] = f2t(__uint_as_float(qbase[(size_t)(rb + r4 + 8) * QKV_STRIDE + col]) * QS);
            qf[kb][m2][2] = f2t(__uint_as_float(qbase[(size_t)(rb + r4) * QKV_STRIDE + col + 4]) * QS);
            qf[kb][m2][3] = f2t(__uint_as_float(qbase[(size_t)(rb + r4 + 8) * QKV_STRIDE + col + 4]) * QS);
        }
    }

    issueKV(0, 0);

    float mrun[2][2] = {{-3.0e38f, -3.0e38f}, {-3.0e38f, -3.0e38f}};
    float lrun[2][2] = {{0.f, 0.f}, {0.f, 0.f}};
    float o[2][8][4] = {};
    uint32_t* Pw = Psm + warp * 2048;

    for (int t = 0; t < 16; t++) {
        const int s = t & 1;
        asm volatile("cp.async.wait_group 0;" ::: "memory");
        __syncthreads();

        const uint32_t* Ksm = sm + s * KVBUF;
        const uint32_t* Vsm = sm + (2 + s) * KVBUF;

        // ---- S = Q * K^T ----
        float sv[2][8][4] = {};
        #pragma unroll
        for (int kb = 0; kb < 8; kb++) {
            #pragma unroll
            for (int fn = 0; fn < 8; fn++) {
                uint32_t bb[2];
                bb[0] = Ksm[(fn * 8 + r4) * KVPAD + kb * 8 + c4];
                bb[1] = Ksm[(fn * 8 + r4) * KVPAD + kb * 8 + c4 + 4];
                mma8(sv[0][fn], qf[kb][0], bb);
                mma8(sv[1][fn], qf[kb][1], bb);
            }
        }

        // prefetch next tile (after MMAs — R14 ordering lesson)
        if (t + 1 < 16) issueKV(t + 1, s ^ 1);

        // ---- online softmax (exp2 domain) ----
        #pragma unroll
        for (int m2 = 0; m2 < 2; m2++) {
            float mt0 = -3.0e38f, mt1 = -3.0e38f;
            #pragma unroll
            for (int fn = 0; fn < 8; fn++) {
                mt0 = fmaxf(mt0, fmaxf(sv[m2][fn][0], sv[m2][fn][1]));
                mt1 = fmaxf(mt1, fmaxf(sv[m2][fn][2], sv[m2][fn][3]));
            }
            mt0 = fmaxf(mt0, __shfl_xor_sync(0xffffffffu, mt0, 1));
            mt0 = fmaxf(mt0, __shfl_xor_sync(0xffffffffu, mt0, 2));
            mt1 = fmaxf(mt1, __shfl_xor_sync(0xffffffffu, mt1, 1));
            mt1 = fmaxf(mt1, __shfl_xor_sync(0xffffffffu, mt1, 2));
            const float mn0 = fmaxf(mrun[m2][0], mt0);
            const float mn1 = fmaxf(mrun[m2][1], mt1);
            const float al0 = ex2(mrun[m2][0] - mn0);
            const float al1 = ex2(mrun[m2][1] - mn1);
            float ls0 = 0.f, ls1 = 0.f;
            #pragma unroll
            for (int fn = 0; fn < 8; fn++) {
                sv[m2][fn][0] = ex2(sv[m2][fn][0] - mn0); ls0 += sv[m2][fn][0];
                sv[m2][fn][1] = ex2(sv[m2][fn][1] - mn0); ls0 += sv[m2][fn][1];
                sv[m2][fn][2] = ex2(sv[m2][fn][2] - mn1); ls1 += sv[m2][fn][2];
                sv[m2][fn][3] = ex2(sv[m2][fn][3] - mn1); ls1 += sv[m2][fn][3];
            }
            ls0 += __shfl_xor_sync(0xffffffffu, ls0, 1);
            ls0 += __shfl_xor_sync(0xffffffffu, ls0, 2);
            ls1 += __shfl_xor_sync(0xffffffffu, ls1, 1);
            ls1 += __shfl_xor_sync(0xffffffffu, ls1, 2);
            lrun[m2][0] = lrun[m2][0] * al0 + ls0;
            lrun[m2][1] = lrun[m2][1] * al1 + ls1;
            mrun[m2][0] = mn0;  mrun[m2][1] = mn1;

            #pragma unroll
            for (int fn = 0; fn < 8; fn++) {
                o[m2][fn][0] *= al0; o[m2][fn][1] *= al0;
                o[m2][fn][2] *= al1; o[m2][fn][3] *= al1;
            }

            const int lp0 = r4 * 4 + 2 * (c4 & 1);
            const int rb  = 2 * (c4 >> 1);
            uint32_t* Pm = Pw + m2 * 1024;
            #pragma unroll
            for (int fn = 0; fn < 8; fn++) {
                Pm[(fn * 4 + rb) * 32 + lp0]         = f2t(sv[m2][fn][0]);
                Pm[(fn * 4 + rb) * 32 + lp0 + 1]     = f2t(sv[m2][fn][1]);
                Pm[(fn * 4 + rb + 1) * 32 + lp0]     = f2t(sv[m2][fn][2]);
                Pm[(fn * 4 + rb + 1) * 32 + lp0 + 1] = f2t(sv[m2][fn][3]);
            }
        }
        __syncwarp();

        // ---- O += P * V (plain-row V^T, conflict-free) ----
        #pragma unroll
        for (int kb = 0; kb < 8; kb++) {
            uint32_t a0[4], a1[4];
            #pragma unroll
            for (int r = 0; r < 4; r++) {
                a0[r] = Pw[(kb * 4 + r) * 32 + lane];
                a1[r] = Pw[1024 + (kb * 4 + r) * 32 + lane];
            }
            #pragma unroll
            for (int fn = 0; fn < 8; fn++) {
                const int d = fn * 8 + r4;
                uint32_t bb[2];
                bb[0] = Vsm[d * KVPAD + kb * 8 + c4];
                bb[1] = Vsm[d * KVPAD + kb * 8 + c4 + 4];
                mma8(o[0][fn], a0, bb);
                mma8(o[1][fn], a1, bb);
            }
        }
        __syncwarp();
    }

    // ---- normalize, emit tf32 bits for GEMM2 ----
    #pragma unroll
    for (int m2 = 0; m2 < 2; m2++) {
        const float inv0 = 1.f / lrun[m2][0];
        const float inv1 = 1.f / lrun[m2][1];
        uint32_t* ob = out + ((size_t)b * SEQ + qr0 + m2 * 16) * INNER + h * DH;
        #pragma unroll
        for (int fn = 0; fn < 8; fn++) {
            const int col = fn * 8 + 2 * c4;
            *(uint2*)&ob[(size_t)r4 * INNER + col] =
                make_uint2(f2t(o[m2][fn][0] * inv0), f2t(o[m2][fn][1] * inv0));
            *(uint2*)&ob[(size_t)(r4 + 8) * INNER + col] =
                make_uint2(f2t(o[m2][fn][2] * inv1), f2t(o[m2][fn][3] * inv1));
        }
    }
}

// ---------------------------------------------------------------------------
// Launch
// ---------------------------------------------------------------------------
extern "C" void kernel_launch(void* const* d_in, const int* in_sizes, int n_in,
                              void* d_out, int out_size)
{
    const float* x      = (const float*)d_in[0];
    const float* w_qkv  = (const float*)d_in[1];
    const float* w_out  = (const float*)d_in[2];
    const float* b_out  = (const float*)d_in[3];
    uint32_t* out = (uint32_t*)d_out;

    uint32_t *qkv, *vt, *att, *xt, *wqkvt, *woutt;
    cudaGetSymbolAddress((void**)&qkv,   g_qkv);
    cudaGetSymbolAddress((void**)&vt,    g_vt);
    cudaGetSymbolAddress((void**)&att,   g_att);
    cudaGetSymbolAddress((void**)&xt,    g_xt);
    cudaGetSymbolAddress((void**)&wqkvt, g_wqkvt);
    cudaGetSymbolAddress((void**)&woutt, g_woutt);

    const int M = BATCH * SEQ;   // 8192

    cudaFuncSetAttribute(gemm_tf32, cudaFuncAttributeMaxDynamicSharedMemorySize, GEMM_SMEM);
    cudaFuncSetAttribute(attn_tf32, cudaFuncAttributeMaxDynamicSharedMemorySize, ATTN_SMEM);

    // 0) pre-convert all operands to tf32 bits (single fused launch)
    conv_all<<<2048, 256>>>(
        (const float4*)x,     (uint4*)xt,    (int)((size_t)M * DIM / 4),
        (const float4*)w_qkv, (uint4*)wqkvt, (int)((size_t)DIM * 3 * INNER / 4),
        (const float4*)w_out, (uint4*)woutt, (int)((size_t)INNER * DIM / 4));

    // 1) QKV projection (tf32 bits; V written transposed into g_vt)
    gemm_tf32<<<dim3(3 * INNER / 128, M / 128), 128, GEMM_SMEM>>>(
        xt, wqkvt, nullptr, qkv, vt, M, 3 * INNER, DIM, 1);

    // 2) Flash attention (emits tf32 bits)
    attn_tf32<<<dim3(SEQ / 128, HEADS, BATCH), 128, ATTN_SMEM>>>(qkv, vt, att);

    // 3) Output projection (fp32 + bias, final)
    gemm_tf32<<<dim3(DIM / 128, M / 128), 128, GEMM_SMEM>>>(
        att, woutt, b_out, out, nullptr, M, DIM, INNER, 0);
}